// round 4
// baseline (speedup 1.0000x reference)
#include <cuda_runtime.h>
#include <math.h>

// ---------------- constants ----------------
#define D_IN  768
#define NHD   8          // heads
#define HD    96         // head dim
#define HID   768
#define UPD   1536
#define FUSED 2320
#define CSZ   64         // chunk size
#define NCC   64         // chunks per (b,h)  = 4096/64
#define BB    2
#define SS    4096
#define TT    (BB*SS)    // 8192 tokens
#define NBH   (BB*NHD)   // 16
#define NBLK  (NBH*NCC)  // 1024 chunk blocks
#define CAPV  15.0f
#define EPSV  1e-6f
#define KSCALE 0.1020620726159657f  // 1/sqrt(96)

// ---------------- scratch (device globals, no allocation) ----------------
__device__ float g_xn  [(size_t)TT*D_IN];
__device__ float g_xt  [(size_t)TT*UPD];
__device__ float g_rt  [(size_t)TT*HID];
__device__ float g_xc  [(size_t)TT*UPD];
__device__ float g_skip[(size_t)TT*HID];
__device__ float g_proj[(size_t)TT*FUSED];
__device__ float g_o   [(size_t)TT*HID];
__device__ float g_h   [(size_t)TT*HID];
__device__ float g_g   [(size_t)TT*HID];
__device__ float g_C   [(size_t)NBLK*HD*HD];
__device__ float g_n   [(size_t)NBLK*HD];
__device__ float g_lf  [(size_t)NBLK*CSZ];
__device__ float g_ig  [(size_t)NBLK*CSZ];
__device__ int   g_canflag[32];

// ---------------- diagnostics ----------------
__global__ void canary_reset_kernel() {
    if (threadIdx.x < 32) g_canflag[threadIdx.x] = 0;
}
__global__ void canary_kernel(const float* __restrict__ buf, size_t n, int id) {
    size_t i = (size_t)blockIdx.x * blockDim.x + threadIdx.x;
    const size_t stride = (size_t)gridDim.x * blockDim.x;
    for (; i < n; i += stride) {
        float v = buf[i];
        if (!isfinite(v)) { g_canflag[id] = 1; return; }
    }
}
__global__ void scrub_kernel(float* __restrict__ out, size_t n) {
    size_t i = (size_t)blockIdx.x * blockDim.x + threadIdx.x;
    const size_t stride = (size_t)gridDim.x * blockDim.x;
    for (; i < n; i += stride) {
        float v = out[i];
        if (!isfinite(v)) out[i] = 0.f;
    }
}
__global__ void marker_kernel(float* __restrict__ out, int size_mismatch) {
    if (threadIdx.x != 0 || blockIdx.x != 0) return;
    int first = -1;
    for (int k = 0; k < 20; k++)
        if (g_canflag[k]) { first = k; break; }
    float m = 0.f;
    if (size_mismatch)   m = 3.0e38f;
    else if (first >= 0) m = exp2f(24.f + 7.f * (float)first);
    if (m != 0.f) out[0] = m;
}

// ---------------- block reduce helper (256 threads, sum) ----------------
__device__ __forceinline__ float block_sum_256(float v, float* red) {
    for (int o = 16; o; o >>= 1) v += __shfl_xor_sync(~0u, v, o);
    const int wid = threadIdx.x >> 5;
    if ((threadIdx.x & 31) == 0) red[wid] = v;
    __syncthreads();
    if (threadIdx.x < 32) {
        float s = (threadIdx.x < 8) ? red[threadIdx.x] : 0.f;
        for (int o = 4; o; o >>= 1) s += __shfl_xor_sync(~0u, s, o);
        if (threadIdx.x == 0) red[8] = s;
    }
    __syncthreads();
    float r = red[8];
    __syncthreads();
    return r;
}

// ---------------- LayerNorm over 768 (two-pass: matches reference overflow semantics) ----------------
__global__ void __launch_bounds__(256) ln_kernel(const float* __restrict__ x,
                                                 const float* __restrict__ w,
                                                 const float* __restrict__ b,
                                                 float* __restrict__ y) {
    __shared__ float red[9];
    const int t = blockIdx.x;
    const float* xr = x + (size_t)t * 768;
    float v0 = xr[threadIdx.x], v1 = xr[threadIdx.x + 256], v2 = xr[threadIdx.x + 512];
    const float mean = block_sum_256(v0 + v1 + v2, red) * (1.f / 768.f);
    float d0 = v0 - mean, d1 = v1 - mean, d2 = v2 - mean;
    const float var = block_sum_256(d0 * d0 + d1 * d1 + d2 * d2, red) * (1.f / 768.f);
    const float rstd = rsqrtf(var + EPSV);
    float* yr = y + (size_t)t * 768;
    yr[threadIdx.x]       = d0 * rstd * w[threadIdx.x]       + b[threadIdx.x];
    yr[threadIdx.x + 256] = d1 * rstd * w[threadIdx.x + 256] + b[threadIdx.x + 256];
    yr[threadIdx.x + 512] = d2 * rstd * w[threadIdx.x + 512] + b[threadIdx.x + 512];
}

// ---------------- SGEMM: C[M,N] = A[M,K] @ W[K,N] + bias, epilogues ----------------
// epi 0: none; 1: sigmoid; 2: += res (res shape == C)
__global__ void __launch_bounds__(256) sgemm_kernel(const float* __restrict__ A,
                                                    const float* __restrict__ W,
                                                    const float* __restrict__ bias,
                                                    float* __restrict__ Cout,
                                                    int M, int N, int K, int epi,
                                                    const float* __restrict__ res) {
    __shared__ float As[16][64];
    __shared__ float Bs[16][68];
    const int tid = threadIdx.x;
    const int tx = tid & 15, ty = tid >> 4;
    const int m0 = blockIdx.y << 6, n0 = blockIdx.x << 6;
    float acc[4][4] = {};
    const int arow = tid >> 2, akq = (tid & 3) << 2;
    const int brow = tid >> 4, bcq = (tid & 15) << 2;
    const bool fullN = (n0 + 64 <= N);
    for (int k0 = 0; k0 < K; k0 += 16) {
        float4 av = *(const float4*)(A + (size_t)(m0 + arow) * K + k0 + akq);
        As[akq + 0][arow] = av.x; As[akq + 1][arow] = av.y;
        As[akq + 2][arow] = av.z; As[akq + 3][arow] = av.w;
        const float* wp = W + (size_t)(k0 + brow) * N + n0 + bcq;
        float4 bv;
        if (fullN) {
            bv = *(const float4*)wp;
        } else {
            bv.x = (n0 + bcq + 0 < N) ? wp[0] : 0.f;
            bv.y = (n0 + bcq + 1 < N) ? wp[1] : 0.f;
            bv.z = (n0 + bcq + 2 < N) ? wp[2] : 0.f;
            bv.w = (n0 + bcq + 3 < N) ? wp[3] : 0.f;
        }
        Bs[brow][bcq + 0] = bv.x; Bs[brow][bcq + 1] = bv.y;
        Bs[brow][bcq + 2] = bv.z; Bs[brow][bcq + 3] = bv.w;
        __syncthreads();
#pragma unroll
        for (int kk = 0; kk < 16; kk++) {
            float ar[4], br[4];
#pragma unroll
            for (int i = 0; i < 4; i++) ar[i] = As[kk][ty * 4 + i];
#pragma unroll
            for (int j = 0; j < 4; j++) br[j] = Bs[kk][tx * 4 + j];
#pragma unroll
            for (int i = 0; i < 4; i++)
#pragma unroll
                for (int j = 0; j < 4; j++) acc[i][j] += ar[i] * br[j];
        }
        __syncthreads();
    }
#pragma unroll
    for (int i = 0; i < 4; i++) {
        const int row = m0 + ty * 4 + i;
#pragma unroll
        for (int j = 0; j < 4; j++) {
            const int col = n0 + tx * 4 + j;
            if (col < N) {
                float v = acc[i][j] + bias[col];
                if (epi == 1)      v = 1.f / (1.f + expf(-v));
                else if (epi == 2) v += res[(size_t)row * N + col];
                Cout[(size_t)row * N + col] = v;
            }
        }
    }
}

// ---------------- causal conv (K=4) + SiLU ----------------
__global__ void conv_silu_kernel(const float* __restrict__ xt,
                                 const float* __restrict__ cw,
                                 const float* __restrict__ cb,
                                 float* __restrict__ xc) {
    const size_t idx = (size_t)blockIdx.x * blockDim.x + threadIdx.x;
    if (idx >= (size_t)TT * UPD) return;
    const int tok = (int)(idx / UPD);
    const int t = tok % SS;
    float acc = cb[0];
    const float* base = xt + idx;
    acc += cw[3] * base[0];
    if (t >= 1) acc += cw[2] * base[-(ptrdiff_t)UPD];
    if (t >= 2) acc += cw[1] * base[-2 * (ptrdiff_t)UPD];
    if (t >= 3) acc += cw[0] * base[-3 * (ptrdiff_t)UPD];
    xc[idx] = acc / (1.f + expf(-acc));
}

// ---------------- phase A: gates + chunk contributions ----------------
__global__ void __launch_bounds__(256) phaseA_kernel() {
    extern __shared__ float sm[];
    float* kS = sm;                  // 64*96
    float* vS = kS + 64 * 96;        // 64*96
    float* lf = vS + 64 * 96;        // 64
    float* ig = lf + 64;             // 64
    float* wC = ig + 64;             // 64
    const int tid = threadIdx.x;
    const int blk = blockIdx.x;
    const int c = blk % NCC; const int bh = blk / NCC;
    const int h = bh % NHD;  const int b = bh / NHD;
    const int tok0 = b * SS + c * CSZ;

    if (tid < 64) {
        const float* p = g_proj + (size_t)(tok0 + tid) * FUSED;
        float ip = CAPV * tanhf(p[h] / CAPV);
        float fp = CAPV * tanhf(p[NHD + h] / CAPV);
        float mx = fmaxf(ip, fp);
        float igv = expf(ip - mx);
        float fgv = expf(fp - mx);
        ig[tid] = igv;
        lf[tid] = logf(fgv + 1e-8f);
    }
    __syncthreads();
    if (tid == 0) { float r = 0.f; for (int l = 0; l < 64; l++) { r += lf[l]; lf[l] = r; } }
    __syncthreads();
    if (tid < 64) {
        wC[tid] = expf(lf[tid] - lf[63]) * ig[tid];
        g_lf[(size_t)blk * 64 + tid] = lf[tid];
        g_ig[(size_t)blk * 64 + tid] = ig[tid];
    }
    for (int idx = tid; idx < 64 * 96; idx += 256) {
        const int l = idx / 96, e = idx - l * 96;
        const float* p = g_proj + (size_t)(tok0 + l) * FUSED + 2 * NHD + h * HD + e;
        kS[idx] = p[HID] * KSCALE;
        vS[idx] = p[2 * HID];
    }
    __syncthreads();
    for (int idx = tid; idx < 64 * 96; idx += 256) vS[idx] *= wC[idx / 96];
    __syncthreads();
    float* outC = g_C + (size_t)blk * HD * HD;
    for (int idx = tid; idx < HD * HD; idx += 256) {
        const int d = idx / HD, e = idx - d * HD;
        float s = 0.f;
#pragma unroll 8
        for (int l = 0; l < 64; l++) s += vS[l * 96 + d] * kS[l * 96 + e];
        outC[idx] = s;
    }
    if (tid < HD) {
        float s = 0.f;
#pragma unroll 8
        for (int l = 0; l < 64; l++) s += wC[l] * kS[l * 96 + tid];
        g_n[(size_t)blk * HD + tid] = s;
    }
}

// ---------------- phase B: exclusive prefix over chunks (per b,h) ----------------
__global__ void __launch_bounds__(256) phaseB_kernel() {
    const int bh = blockIdx.x;  // 0..15
    const int tid = threadIdx.x;
    float run[36];
#pragma unroll
    for (int r = 0; r < 36; r++) run[r] = 0.f;
    for (int c = 0; c < NCC; c++) {
        float* p = g_C + (size_t)(bh * NCC + c) * HD * HD;
#pragma unroll
        for (int r = 0; r < 36; r++) {
            const int idx = r * 256 + tid;
            const float t = p[idx];
            p[idx] = run[r];
            run[r] += t;
        }
    }
    if (tid < HD) {
        float rn = 0.f;
        for (int c = 0; c < NCC; c++) {
            float* p = g_n + (size_t)(bh * NCC + c) * HD;
            const float t = p[tid];
            p[tid] = rn;
            rn += t;
        }
    }
}

// ---------------- phase C: intra attention + state readout ----------------
__global__ void __launch_bounds__(256) phaseC_kernel() {
    extern __shared__ float sm[];
    float* qS = sm;                  // 64*96
    float* kS = qS + 6144;
    float* vS = kS + 6144;
    float* hS = vS + 6144;
    float* Ci = hS + 6144;           // 96*96
    float* sc = Ci + 9216;           // 64*64
    float* wS = sc + 4096;           // 64*64
    float* lf = wS + 4096;           // 64
    float* ig = lf + 64;             // 64
    float* nin = ig + 64;            // 96
    float* den = nin + 96;           // 256
    const int tid = threadIdx.x;
    const int blk = blockIdx.x;
    const int c = blk % NCC; const int bh = blk / NCC;
    const int h = bh % NHD;  const int b = bh / NHD;
    const int tok0 = b * SS + c * CSZ;

    for (int idx = tid; idx < 64 * 96; idx += 256) {
        const int l = idx / 96, e = idx - l * 96;
        const float* p = g_proj + (size_t)(tok0 + l) * FUSED + 2 * NHD + h * HD + e;
        qS[idx] = p[0];
        kS[idx] = p[HID] * KSCALE;
        vS[idx] = p[2 * HID];
    }
    for (int idx = tid; idx < 9216; idx += 256) Ci[idx] = g_C[(size_t)blk * 9216 + idx];
    if (tid < 96) nin[tid] = g_n[(size_t)blk * HD + tid];
    if (tid < 64) { lf[tid] = g_lf[(size_t)blk * 64 + tid]; ig[tid] = g_ig[(size_t)blk * 64 + tid]; }
    __syncthreads();

    for (int idx = tid; idx < 4096; idx += 256) {
        const int i = idx >> 6, j = idx & 63;
        const float* qi = qS + i * 96;
        const float* kj = kS + j * 96;
        float s = 0.f;
#pragma unroll 8
        for (int e = 0; e < 96; e++) s += qi[e] * kj[e];
        sc[idx] = s;
        wS[idx] = (j < i) ? ig[j] * expf(lf[i] - lf[j]) : 0.f;
    }
    __syncthreads();

    if (tid < 64) {
        const int i = tid;
        float* row = sc + i * 64;
        if (i == 0) {
            for (int j = 0; j < 64; j++) row[j] = 0.f;
        } else {
            float m = -1e30f;
            for (int j = 0; j < i; j++) m = fmaxf(m, row[j]);
            float sum = 0.f;
            for (int j = 0; j < i; j++) { float e = expf(row[j] - m); row[j] = e; sum += e; }
            const float inv = 1.f / sum;
            for (int j = 0; j < i; j++) row[j] = row[j] * inv * wS[i * 64 + j];
            for (int j = i; j < 64; j++) row[j] = 0.f;
        }
    }
    __syncthreads();

    {
        const int i = tid >> 2, dg = tid & 3;
        const float* sci = sc + i * 64;
        const float* wi  = wS + i * 64;
        const float* qi  = qS + i * 96;
        float dpart = 0.f;
#pragma unroll 4
        for (int t2 = 0; t2 < 24; t2++) {
            const int d = dg * 24 + t2;
            float hv = 0.f, nv = nin[d];
#pragma unroll 8
            for (int j = 0; j < 64; j++) {
                hv += sci[j] * vS[j * 96 + d];
                nv += wi[j]  * kS[j * 96 + d];
            }
            const float* cd = Ci + d * 96;
#pragma unroll 8
            for (int e = 0; e < 96; e++) hv += cd[e] * qi[e];
            hS[i * 96 + d] = hv;
            dpart += nv * qi[d];
        }
        den[tid] = dpart;
    }
    __syncthreads();

    for (int idx = tid; idx < 6144; idx += 256) {
        const int i = idx / 96, d = idx - i * 96;
        const float dn = fmaxf(den[i * 4] + den[i * 4 + 1] + den[i * 4 + 2] + den[i * 4 + 3], 1.f);
        g_h[(size_t)(tok0 + i) * HID + h * HD + d] = hS[idx] / dn;
    }
}

// ---------------- combine: o*h, LN_hid (two-pass), +skip, *silu(r) ----------------
__global__ void __launch_bounds__(256) combine_kernel(const float* __restrict__ w,
                                                      const float* __restrict__ b) {
    __shared__ float red[9];
    const int t = blockIdx.x;
    const size_t off = (size_t)t * 768 + threadIdx.x;
    float h0 = g_h[off]       * g_o[off];
    float h1 = g_h[off + 256] * g_o[off + 256];
    float h2 = g_h[off + 512] * g_o[off + 512];
    const float mean = block_sum_256(h0 + h1 + h2, red) * (1.f / 768.f);
    float d0 = h0 - mean, d1 = h1 - mean, d2 = h2 - mean;
    // (x-mean)^2 formulation: overflow saturates to +inf -> rstd -> 0 (matches reference)
    const float var = block_sum_256(d0 * d0 + d1 * d1 + d2 * d2, red) * (1.f / 768.f);
    const float rstd = rsqrtf(var + EPSV);
#pragma unroll
    for (int kk = 0; kk < 3; kk++) {
        const int d = threadIdx.x + kk * 256;
        const size_t o2 = (size_t)t * 768 + d;
        const float dv = (kk == 0 ? d0 : (kk == 1 ? d1 : d2));
        float g = dv * rstd * w[d] + b[d] + g_skip[o2];
        const float r = g_rt[o2];
        g *= r / (1.f + expf(-r));
        g_g[o2] = g;
    }
}

// ---------------- launch ----------------
#define GETSYM(var, sym) float* var; { void* _p = nullptr; cudaGetSymbolAddress(&_p, sym); var = (float*)_p; }

extern "C" void kernel_launch(void* const* d_in, const int* in_sizes, int n_in,
                              void* d_out, int out_size) {
    const float* x        = (const float*)d_in[0];
    const float* ln_in_w  = (const float*)d_in[1];
    const float* ln_in_b  = (const float*)d_in[2];
    const float* ln_hid_w = (const float*)d_in[3];
    const float* ln_hid_b = (const float*)d_in[4];
    const float* up_l_w   = (const float*)d_in[5];
    const float* up_l_b   = (const float*)d_in[6];
    const float* up_r_w   = (const float*)d_in[7];
    const float* up_r_b   = (const float*)d_in[8];
    const float* down_w   = (const float*)d_in[9];
    const float* down_b   = (const float*)d_in[10];
    const float* conv_w   = (const float*)d_in[11];
    const float* conv_b   = (const float*)d_in[12];
    const float* skip_w   = (const float*)d_in[13];
    const float* skip_b   = (const float*)d_in[14];
    const float* fused_w  = (const float*)d_in[15];
    const float* fused_b  = (const float*)d_in[16];
    const float* wo_w     = (const float*)d_in[17];
    const float* wo_b     = (const float*)d_in[18];
    float* out = (float*)d_out;

    const int expect[19] = {
        TT * D_IN, D_IN, D_IN, HID, HID,
        D_IN * UPD, UPD, D_IN * HID, HID,
        HID * D_IN, D_IN, 4, 1,
        UPD * HID, HID, UPD * FUSED, FUSED, UPD * HID, HID
    };
    int size_mismatch = (n_in != 19) ? 1 : 0;
    for (int i = 0; i < 19 && !size_mismatch && i < n_in; i++)
        if (in_sizes[i] != expect[i]) size_mismatch = 1;

    GETSYM(p_xn, g_xn);   GETSYM(p_xt, g_xt);   GETSYM(p_rt, g_rt);
    GETSYM(p_xc, g_xc);   GETSYM(p_skip, g_skip); GETSYM(p_proj, g_proj);
    GETSYM(p_o, g_o);     GETSYM(p_g, g_g);     GETSYM(p_h, g_h);
    GETSYM(p_C, g_C);     GETSYM(p_lf, g_lf);

    const int smemA = (2 * 64 * 96 + 3 * 64) * 4;
    const int smemC = (4 * 6144 + 9216 + 2 * 4096 + 64 + 64 + 96 + 256) * 4;
    cudaFuncSetAttribute(phaseA_kernel, cudaFuncAttributeMaxDynamicSharedMemorySize, smemA);
    cudaFuncSetAttribute(phaseC_kernel, cudaFuncAttributeMaxDynamicSharedMemorySize, smemC);

    canary_reset_kernel<<<1, 32>>>();

    ln_kernel<<<TT, 256>>>(x, ln_in_w, ln_in_b, p_xn);
    canary_kernel<<<1024, 256>>>(p_xn, (size_t)TT * D_IN, 1);
    sgemm_kernel<<<dim3(UPD / 64, TT / 64), 256>>>(p_xn, up_l_w, up_l_b, p_xt, TT, UPD, D_IN, 0, nullptr);
    canary_kernel<<<1024, 256>>>(p_xt, (size_t)TT * UPD, 2);
    sgemm_kernel<<<dim3(HID / 64, TT / 64), 256>>>(p_xn, up_r_w, up_r_b, p_rt, TT, HID, D_IN, 0, nullptr);
    canary_kernel<<<1024, 256>>>(p_rt, (size_t)TT * HID, 3);
    conv_silu_kernel<<<(int)(((size_t)TT * UPD + 255) / 256), 256>>>(p_xt, conv_w, conv_b, p_xc);
    canary_kernel<<<1024, 256>>>(p_xc, (size_t)TT * UPD, 4);
    sgemm_kernel<<<dim3((FUSED + 63) / 64, TT / 64), 256>>>(p_xc, fused_w, fused_b, p_proj, TT, FUSED, UPD, 0, nullptr);
    canary_kernel<<<1024, 256>>>(p_proj, (size_t)TT * FUSED, 5);
    sgemm_kernel<<<dim3(HID / 64, TT / 64), 256>>>(p_xc, skip_w, skip_b, p_skip, TT, HID, UPD, 0, nullptr);
    canary_kernel<<<1024, 256>>>(p_skip, (size_t)TT * HID, 6);
    sgemm_kernel<<<dim3(HID / 64, TT / 64), 256>>>(p_xt, wo_w, wo_b, p_o, TT, HID, UPD, 1, nullptr);
    canary_kernel<<<1024, 256>>>(p_o, (size_t)TT * HID, 7);
    phaseA_kernel<<<NBLK, 256, smemA>>>();
    canary_kernel<<<1024, 256>>>(p_C, (size_t)NBLK * HD * HD, 8);
    canary_kernel<<<64, 256>>>(p_lf, (size_t)NBLK * CSZ, 9);
    phaseB_kernel<<<NBH, 256>>>();
    canary_kernel<<<1024, 256>>>(p_C, (size_t)NBLK * HD * HD, 10);
    phaseC_kernel<<<NBLK, 256, smemC>>>();
    canary_kernel<<<1024, 256>>>(p_h, (size_t)TT * HID, 11);
    combine_kernel<<<TT, 256>>>(ln_hid_w, ln_hid_b);
    canary_kernel<<<1024, 256>>>(p_g, (size_t)TT * HID, 12);
    sgemm_kernel<<<dim3(HID / 64, TT / 64), 256>>>(p_g, down_w, down_b, out, TT, D_IN, HID, 2, x);
    canary_kernel<<<1024, 256>>>(out, (size_t)TT * D_IN, 13);

    scrub_kernel<<<4096, 256>>>(out, (size_t)TT * D_IN);
    marker_kernel<<<1, 32>>>(out, size_mismatch);
}

// round 8
// speedup vs baseline: 1.0019x; 1.0019x over previous
#include <cuda_runtime.h>
#include <math.h>

// ---------------- constants ----------------
#define D_IN  768
#define NHD   8
#define HD    96
#define HID   768
#define UPD   1536
#define FUSED 2320
#define CSZ   64
#define NCC   64
#define BB    2
#define SS    4096
#define TT    (BB*SS)
#define NBH   (BB*NHD)
#define NBLK  (NBH*NCC)
#define CAPV  15.0f
#define EPSV  1e-6f
#define KSCALE 0.1020620726159657f  // 1/sqrt(96)

// ---------------- scratch ----------------
__device__ float g_xn  [(size_t)TT*D_IN];
__device__ float g_xt  [(size_t)TT*UPD];
__device__ float g_rt  [(size_t)TT*HID];
__device__ float g_xc  [(size_t)TT*UPD];
__device__ float g_skip[(size_t)TT*HID];
__device__ float g_proj[(size_t)TT*FUSED];
__device__ float g_o   [(size_t)TT*HID];
__device__ float g_h   [(size_t)TT*HID];
__device__ float g_g   [(size_t)TT*HID];
__device__ float g_C   [(size_t)NBLK*HD*HD];
__device__ float g_n   [(size_t)NBLK*HD];
__device__ float g_lf  [(size_t)NBLK*CSZ];
__device__ float g_ig  [(size_t)NBLK*CSZ];

// ---------------- block reduce (256 threads, sum) ----------------
__device__ __forceinline__ float block_sum_256(float v, float* red) {
    for (int o = 16; o; o >>= 1) v += __shfl_xor_sync(~0u, v, o);
    const int wid = threadIdx.x >> 5;
    if ((threadIdx.x & 31) == 0) red[wid] = v;
    __syncthreads();
    if (threadIdx.x < 32) {
        float s = (threadIdx.x < 8) ? red[threadIdx.x] : 0.f;
        for (int o = 4; o; o >>= 1) s += __shfl_xor_sync(~0u, s, o);
        if (threadIdx.x == 0) red[8] = s;
    }
    __syncthreads();
    float r = red[8];
    __syncthreads();
    return r;
}

// ---------------- LayerNorm (two-pass) ----------------
__global__ void __launch_bounds__(256) ln_kernel(const float* __restrict__ x,
                                                 const float* __restrict__ w,
                                                 const float* __restrict__ b,
                                                 float* __restrict__ y) {
    __shared__ float red[9];
    const int t = blockIdx.x;
    const float* xr = x + (size_t)t * 768;
    float v0 = xr[threadIdx.x], v1 = xr[threadIdx.x + 256], v2 = xr[threadIdx.x + 512];
    const float mean = block_sum_256(v0 + v1 + v2, red) * (1.f / 768.f);
    float d0 = v0 - mean, d1 = v1 - mean, d2 = v2 - mean;
    const float var = block_sum_256(d0 * d0 + d1 * d1 + d2 * d2, red) * (1.f / 768.f);
    const float rstd = rsqrtf(var + EPSV);
    float* yr = y + (size_t)t * 768;
    yr[threadIdx.x]       = d0 * rstd * w[threadIdx.x]       + b[threadIdx.x];
    yr[threadIdx.x + 256] = d1 * rstd * w[threadIdx.x + 256] + b[threadIdx.x + 256];
    yr[threadIdx.x + 512] = d2 * rstd * w[threadIdx.x + 512] + b[threadIdx.x + 512];
}

// ---------------- SGEMM 128x128 tile, 8x8 micro, double buffered ----------------
// C[M,N] = A[M,K]@W[K,N] + bias; epi 0 none, 1 sigmoid, 2 +res
// Requires: M % 128 == 0, K % 8 == 0. N arbitrary (guarded).
__global__ void __launch_bounds__(256) sgemm128_kernel(const float* __restrict__ A,
                                                       const float* __restrict__ W,
                                                       const float* __restrict__ bias,
                                                       float* __restrict__ Cout,
                                                       int M, int N, int K, int epi,
                                                       const float* __restrict__ res) {
    __shared__ float As[2][8][128];
    __shared__ float Bs[2][8][128];
    const int tid = threadIdx.x;
    const int tx = tid & 15, ty = tid >> 4;
    const int m0 = blockIdx.y << 7, n0 = blockIdx.x << 7;
    const int arow = tid >> 1, akq = (tid & 1) << 2;   // A: 128 rows x 8 k
    const int brow = tid >> 5, bcol = (tid & 31) << 2; // B: 8 k x 128 cols
    const bool fullN = (n0 + 128 <= N);
    float acc[8][8] = {};

    const float* aptr = A + (size_t)(m0 + arow) * K + akq;
    // prologue
    {
        float4 av = *(const float4*)(aptr);
        As[0][akq + 0][arow] = av.x; As[0][akq + 1][arow] = av.y;
        As[0][akq + 2][arow] = av.z; As[0][akq + 3][arow] = av.w;
        const float* wp = W + (size_t)brow * N + n0 + bcol;
        float4 bv;
        if (fullN) bv = *(const float4*)wp;
        else {
            bv.x = (n0 + bcol + 0 < N) ? wp[0] : 0.f;
            bv.y = (n0 + bcol + 1 < N) ? wp[1] : 0.f;
            bv.z = (n0 + bcol + 2 < N) ? wp[2] : 0.f;
            bv.w = (n0 + bcol + 3 < N) ? wp[3] : 0.f;
        }
        *(float4*)&Bs[0][brow][bcol] = bv;
    }
    __syncthreads();

    int buf = 0;
    for (int k0 = 0; k0 < K; k0 += 8) {
        if (k0 + 8 < K) {
            const int nb = buf ^ 1;
            float4 av = *(const float4*)(aptr + k0 + 8);
            As[nb][akq + 0][arow] = av.x; As[nb][akq + 1][arow] = av.y;
            As[nb][akq + 2][arow] = av.z; As[nb][akq + 3][arow] = av.w;
            const float* wp = W + (size_t)(k0 + 8 + brow) * N + n0 + bcol;
            float4 bv;
            if (fullN) bv = *(const float4*)wp;
            else {
                bv.x = (n0 + bcol + 0 < N) ? wp[0] : 0.f;
                bv.y = (n0 + bcol + 1 < N) ? wp[1] : 0.f;
                bv.z = (n0 + bcol + 2 < N) ? wp[2] : 0.f;
                bv.w = (n0 + bcol + 3 < N) ? wp[3] : 0.f;
            }
            *(float4*)&Bs[nb][brow][bcol] = bv;
        }
#pragma unroll
        for (int kk = 0; kk < 8; kk++) {
            float ar[8], br[8];
            *(float4*)(ar)     = *(const float4*)&As[buf][kk][ty * 8];
            *(float4*)(ar + 4) = *(const float4*)&As[buf][kk][ty * 8 + 4];
            *(float4*)(br)     = *(const float4*)&Bs[buf][kk][tx * 8];
            *(float4*)(br + 4) = *(const float4*)&Bs[buf][kk][tx * 8 + 4];
#pragma unroll
            for (int i = 0; i < 8; i++)
#pragma unroll
                for (int j = 0; j < 8; j++) acc[i][j] = fmaf(ar[i], br[j], acc[i][j]);
        }
        __syncthreads();
        buf ^= 1;
    }

    // epilogue
    float bj[8];
#pragma unroll
    for (int j = 0; j < 8; j++) {
        const int col = n0 + tx * 8 + j;
        bj[j] = (col < N) ? bias[col] : 0.f;
    }
#pragma unroll
    for (int i = 0; i < 8; i++) {
        const int row = m0 + ty * 8 + i;
        float* crow = Cout + (size_t)row * N;
        const float* rrow = (epi == 2) ? (res + (size_t)row * N) : nullptr;
        if (fullN) {
            float v[8];
#pragma unroll
            for (int j = 0; j < 8; j++) {
                v[j] = acc[i][j] + bj[j];
                if (epi == 1) v[j] = 1.f / (1.f + expf(-v[j]));
                else if (epi == 2) v[j] += rrow[n0 + tx * 8 + j];
            }
            *(float4*)&crow[n0 + tx * 8]     = *(float4*)v;
            *(float4*)&crow[n0 + tx * 8 + 4] = *(float4*)(v + 4);
        } else {
#pragma unroll
            for (int j = 0; j < 8; j++) {
                const int col = n0 + tx * 8 + j;
                if (col < N) {
                    float v = acc[i][j] + bj[j];
                    if (epi == 1) v = 1.f / (1.f + expf(-v));
                    else if (epi == 2) v += rrow[col];
                    crow[col] = v;
                }
            }
        }
    }
}

// ---------------- causal conv (K=4) + SiLU ----------------
__global__ void conv_silu_kernel(const float* __restrict__ xt,
                                 const float* __restrict__ cw,
                                 const float* __restrict__ cb,
                                 float* __restrict__ xc) {
    const size_t idx = (size_t)blockIdx.x * blockDim.x + threadIdx.x;
    if (idx >= (size_t)TT * UPD) return;
    const int tok = (int)(idx / UPD);
    const int t = tok % SS;
    float acc = cb[0];
    const float* base = xt + idx;
    acc += cw[3] * base[0];
    if (t >= 1) acc += cw[2] * base[-(ptrdiff_t)UPD];
    if (t >= 2) acc += cw[1] * base[-2 * (ptrdiff_t)UPD];
    if (t >= 3) acc += cw[0] * base[-3 * (ptrdiff_t)UPD];
    xc[idx] = acc / (1.f + expf(-acc));
}

// ---------------- phase A: gates + chunk contributions ----------------
__global__ void __launch_bounds__(256) phaseA_kernel() {
    extern __shared__ float sm[];
    float* kS = sm;
    float* vS = kS + 64 * 96;
    float* lf = vS + 64 * 96;
    float* ig = lf + 64;
    float* wC = ig + 64;
    const int tid = threadIdx.x;
    const int blk = blockIdx.x;
    const int c = blk % NCC; const int bh = blk / NCC;
    const int h = bh % NHD;  const int b = bh / NHD;
    const int tok0 = b * SS + c * CSZ;

    if (tid < 64) {
        const float* p = g_proj + (size_t)(tok0 + tid) * FUSED;
        float ip = CAPV * tanhf(p[h] / CAPV);
        float fp = CAPV * tanhf(p[NHD + h] / CAPV);
        float mx = fmaxf(ip, fp);
        ig[tid] = expf(ip - mx);
        lf[tid] = logf(expf(fp - mx) + 1e-8f);
    }
    __syncthreads();
    if (tid == 0) { float r = 0.f; for (int l = 0; l < 64; l++) { r += lf[l]; lf[l] = r; } }
    __syncthreads();
    if (tid < 64) {
        wC[tid] = expf(lf[tid] - lf[63]) * ig[tid];
        g_lf[(size_t)blk * 64 + tid] = lf[tid];
        g_ig[(size_t)blk * 64 + tid] = ig[tid];
    }
    for (int idx = tid; idx < 64 * 96; idx += 256) {
        const int l = idx / 96, e = idx - l * 96;
        const float* p = g_proj + (size_t)(tok0 + l) * FUSED + 2 * NHD + h * HD + e;
        kS[idx] = p[HID] * KSCALE;
        vS[idx] = p[2 * HID];
    }
    __syncthreads();
    for (int idx = tid; idx < 64 * 96; idx += 256) vS[idx] *= wC[idx / 96];
    __syncthreads();
    float* outC = g_C + (size_t)blk * HD * HD;
    for (int idx = tid; idx < HD * HD; idx += 256) {
        const int d = idx / HD, e = idx - d * HD;
        float s = 0.f;
#pragma unroll 8
        for (int l = 0; l < 64; l++) s += vS[l * 96 + d] * kS[l * 96 + e];
        outC[idx] = s;
    }
    if (tid < HD) {
        float s = 0.f;
#pragma unroll 8
        for (int l = 0; l < 64; l++) s += wC[l] * kS[l * 96 + tid];
        g_n[(size_t)blk * HD + tid] = s;
    }
}

// ---------------- phase B: exclusive prefix over chunks ----------------
__global__ void __launch_bounds__(256) phaseB_kernel() {
    const int bh = blockIdx.x;
    const int tid = threadIdx.x;
    float run[36];
#pragma unroll
    for (int r = 0; r < 36; r++) run[r] = 0.f;
    for (int c = 0; c < NCC; c++) {
        float* p = g_C + (size_t)(bh * NCC + c) * HD * HD;
#pragma unroll
        for (int r = 0; r < 36; r++) {
            const int idx = r * 256 + tid;
            const float t = p[idx];
            p[idx] = run[r];
            run[r] += t;
        }
    }
    if (tid < HD) {
        float rn = 0.f;
        for (int c = 0; c < NCC; c++) {
            float* p = g_n + (size_t)(bh * NCC + c) * HD;
            const float t = p[tid];
            p[tid] = rn;
            rn += t;
        }
    }
}

// ---------------- phase C: intra attention + state readout ----------------
__global__ void __launch_bounds__(256) phaseC_kernel() {
    extern __shared__ float sm[];
    float* qS = sm;
    float* kS = qS + 6144;
    float* vS = kS + 6144;
    float* hS = vS + 6144;
    float* Ci = hS + 6144;           // 96*96
    float* sc = Ci + 9216;           // 64*64
    float* wS = sc + 4096;           // 64*64
    float* lf = wS + 4096;
    float* ig = lf + 64;
    float* nin = ig + 64;
    float* den = nin + 96;
    const int tid = threadIdx.x;
    const int blk = blockIdx.x;
    const int c = blk % NCC; const int bh = blk / NCC;
    const int h = bh % NHD;  const int b = bh / NHD;
    const int tok0 = b * SS + c * CSZ;

    for (int idx = tid; idx < 64 * 96; idx += 256) {
        const int l = idx / 96, e = idx - l * 96;
        const float* p = g_proj + (size_t)(tok0 + l) * FUSED + 2 * NHD + h * HD + e;
        qS[idx] = p[0];
        kS[idx] = p[HID] * KSCALE;
        vS[idx] = p[2 * HID];
    }
    for (int idx = tid; idx < 9216; idx += 256) Ci[idx] = g_C[(size_t)blk * 9216 + idx];
    if (tid < 96) nin[tid] = g_n[(size_t)blk * HD + tid];
    if (tid < 64) { lf[tid] = g_lf[(size_t)blk * 64 + tid]; ig[tid] = g_ig[(size_t)blk * 64 + tid]; }
    __syncthreads();

    for (int idx = tid; idx < 4096; idx += 256) {
        const int i = idx >> 6, j = idx & 63;
        const float* qi = qS + i * 96;
        const float* kj = kS + j * 96;
        float s = 0.f;
#pragma unroll 8
        for (int e = 0; e < 96; e++) s += qi[e] * kj[e];
        sc[idx] = s;
        wS[idx] = (j < i) ? ig[j] * expf(lf[i] - lf[j]) : 0.f;
    }
    __syncthreads();

    if (tid < 64) {
        const int i = tid;
        float* row = sc + i * 64;
        if (i == 0) {
            for (int j = 0; j < 64; j++) row[j] = 0.f;
        } else {
            float m = -1e30f;
            for (int j = 0; j < i; j++) m = fmaxf(m, row[j]);
            float sum = 0.f;
            for (int j = 0; j < i; j++) { float e = expf(row[j] - m); row[j] = e; sum += e; }
            const float inv = 1.f / sum;
            for (int j = 0; j < i; j++) row[j] = row[j] * inv * wS[i * 64 + j];
            for (int j = i; j < 64; j++) row[j] = 0.f;
        }
    }
    __syncthreads();

    {
        const int i = tid >> 2, dg = tid & 3;
        const float* sci = sc + i * 64;
        const float* wi  = wS + i * 64;
        const float* qi  = qS + i * 96;
        float dpart = 0.f;
#pragma unroll 4
        for (int t2 = 0; t2 < 24; t2++) {
            const int d = dg * 24 + t2;
            float hv = 0.f, nv = nin[d];
#pragma unroll 8
            for (int j = 0; j < 64; j++) {
                hv += sci[j] * vS[j * 96 + d];
                nv += wi[j]  * kS[j * 96 + d];
            }
            const float* cd = Ci + d * 96;
#pragma unroll 8
            for (int e = 0; e < 96; e++) hv += cd[e] * qi[e];
            hS[i * 96 + d] = hv;
            dpart += nv * qi[d];
        }
        den[tid] = dpart;
    }
    __syncthreads();

    for (int idx = tid; idx < 6144; idx += 256) {
        const int i = idx / 96, d = idx - i * 96;
        const float dn = fmaxf(den[i * 4] + den[i * 4 + 1] + den[i * 4 + 2] + den[i * 4 + 3], 1.f);
        g_h[(size_t)(tok0 + i) * HID + h * HD + d] = hS[idx] / dn;
    }
}

// ---------------- combine: o*h, LN_hid (two-pass), +skip, *silu(r) ----------------
__global__ void __launch_bounds__(256) combine_kernel(const float* __restrict__ w,
                                                      const float* __restrict__ b) {
    __shared__ float red[9];
    const int t = blockIdx.x;
    const size_t off = (size_t)t * 768 + threadIdx.x;
    float h0 = g_h[off]       * g_o[off];
    float h1 = g_h[off + 256] * g_o[off + 256];
    float h2 = g_h[off + 512] * g_o[off + 512];
    const float mean = block_sum_256(h0 + h1 + h2, red) * (1.f / 768.f);
    float d0 = h0 - mean, d1 = h1 - mean, d2 = h2 - mean;
    const float var = block_sum_256(d0 * d0 + d1 * d1 + d2 * d2, red) * (1.f / 768.f);
    const float rstd = rsqrtf(var + EPSV);
#pragma unroll
    for (int kk = 0; kk < 3; kk++) {
        const int d = threadIdx.x + kk * 256;
        const size_t o2 = (size_t)t * 768 + d;
        const float dv = (kk == 0 ? d0 : (kk == 1 ? d1 : d2));
        float g = dv * rstd * w[d] + b[d] + g_skip[o2];
        const float r = g_rt[o2];
        g *= r / (1.f + expf(-r));
        g_g[o2] = g;
    }
}

// ---------------- launch ----------------
#define GETSYM(var, sym) float* var; { void* _p = nullptr; cudaGetSymbolAddress(&_p, sym); var = (float*)_p; }

extern "C" void kernel_launch(void* const* d_in, const int* in_sizes, int n_in,
                              void* d_out, int out_size) {
    const float* x        = (const float*)d_in[0];
    const float* ln_in_w  = (const float*)d_in[1];
    const float* ln_in_b  = (const float*)d_in[2];
    const float* ln_hid_w = (const float*)d_in[3];
    const float* ln_hid_b = (const float*)d_in[4];
    const float* up_l_w   = (const float*)d_in[5];
    const float* up_l_b   = (const float*)d_in[6];
    const float* up_r_w   = (const float*)d_in[7];
    const float* up_r_b   = (const float*)d_in[8];
    const float* down_w   = (const float*)d_in[9];
    const float* down_b   = (const float*)d_in[10];
    const float* conv_w   = (const float*)d_in[11];
    const float* conv_b   = (const float*)d_in[12];
    const float* skip_w   = (const float*)d_in[13];
    const float* skip_b   = (const float*)d_in[14];
    const float* fused_w  = (const float*)d_in[15];
    const float* fused_b  = (const float*)d_in[16];
    const float* wo_w     = (const float*)d_in[17];
    const float* wo_b     = (const float*)d_in[18];
    float* out = (float*)d_out;

    GETSYM(p_xn, g_xn);   GETSYM(p_xt, g_xt);   GETSYM(p_rt, g_rt);
    GETSYM(p_xc, g_xc);   GETSYM(p_skip, g_skip); GETSYM(p_proj, g_proj);
    GETSYM(p_o, g_o);     GETSYM(p_g, g_g);

    const int smemA = (2 * 64 * 96 + 3 * 64) * 4;
    const int smemC = (4 * 6144 + 9216 + 2 * 4096 + 64 + 64 + 96 + 256) * 4;
    cudaFuncSetAttribute(phaseA_kernel, cudaFuncAttributeMaxDynamicSharedMemorySize, smemA);
    cudaFuncSetAttribute(phaseC_kernel, cudaFuncAttributeMaxDynamicSharedMemorySize, smemC);

    ln_kernel<<<TT, 256>>>(x, ln_in_w, ln_in_b, p_xn);
    sgemm128_kernel<<<dim3(UPD / 128, TT / 128), 256>>>(p_xn, up_l_w, up_l_b, p_xt, TT, UPD, D_IN, 0, nullptr);
    sgemm128_kernel<<<dim3(HID / 128, TT / 128), 256>>>(p_xn, up_r_w, up_r_b, p_rt, TT, HID, D_IN, 0, nullptr);
    conv_silu_kernel<<<(int)(((size_t)TT * UPD + 255) / 256), 256>>>(p_xt, conv_w, conv_b, p_xc);
    sgemm128_kernel<<<dim3((FUSED + 127) / 128, TT / 128), 256>>>(p_xc, fused_w, fused_b, p_proj, TT, FUSED, UPD, 0, nullptr);
    sgemm128_kernel<<<dim3(HID / 128, TT / 128), 256>>>(p_xc, skip_w, skip_b, p_skip, TT, HID, UPD, 0, nullptr);
    sgemm128_kernel<<<dim3(HID / 128, TT / 128), 256>>>(p_xt, wo_w, wo_b, p_o, TT, HID, UPD, 1, nullptr);
    phaseA_kernel<<<NBLK, 256, smemA>>>();
    phaseB_kernel<<<NBH, 256>>>();
    phaseC_kernel<<<NBLK, 256, smemC>>>();
    combine_kernel<<<TT, 256>>>(ln_hid_w, ln_hid_b);
    sgemm128_kernel<<<dim3(HID / 128, TT / 128), 256>>>(p_g, down_w, down_b, out, TT, D_IN, HID, 2, x);
}

// round 16
// speedup vs baseline: 1.1479x; 1.1457x over previous
#include <cuda_runtime.h>
#include <cuda_bf16.h>
#include <math.h>
#include <stdint.h>

// ---------------- constants ----------------
#define D_IN  768
#define NHD   8
#define HD    96
#define HID   768
#define UPD   1536
#define FUSED 2320
#define CSZ   64
#define NCC   64
#define BB    2
#define SS    4096
#define TT    (BB*SS)
#define NBH   (BB*NHD)
#define NBLK  (NBH*NCC)
#define CAPV  15.0f
#define EPSV  1e-6f
#define KSCALE 0.1020620726159657f

#define K2MAX 4608
#define NPMAX 2560

// ---------------- scratch ----------------
__device__ float g_xn  [(size_t)TT*D_IN];
__device__ float g_xt  [(size_t)TT*UPD];
__device__ float g_rt  [(size_t)TT*HID];
__device__ float g_xc  [(size_t)TT*UPD];
__device__ float g_skip[(size_t)TT*HID];
__device__ float g_proj[(size_t)TT*FUSED];
__device__ float g_o   [(size_t)TT*HID];
__device__ float g_h   [(size_t)TT*HID];
__device__ float g_g   [(size_t)TT*HID];
__device__ float g_C   [(size_t)NBLK*HD*HD];
__device__ float g_n   [(size_t)NBLK*HD];
__device__ float g_lf  [(size_t)NBLK*CSZ];
__device__ float g_ig  [(size_t)NBLK*CSZ];
__device__ __align__(16) __nv_bfloat16 g_Abf[(size_t)TT*K2MAX];
__device__ __align__(16) __nv_bfloat16 g_WT [(size_t)NPMAX*K2MAX];

// ---------------- split/convert (bf16 split-2) ----------------
__global__ void convA_kernel(const float* __restrict__ src, __nv_bfloat16* __restrict__ dst, int K) {
    const int k = blockIdx.x * 256 + threadIdx.x;
    const int t = blockIdx.y;
    const float a = src[(size_t)t * K + k];
    const __nv_bfloat16 hi = __float2bfloat16(a);
    const __nv_bfloat16 lo = __float2bfloat16(a - __bfloat162float(hi));
    __nv_bfloat16* row = dst + (size_t)t * (3 * K);
    row[k] = hi; row[K + k] = hi; row[2 * K + k] = lo;
}

__global__ void convW_kernel(const float* __restrict__ W, __nv_bfloat16* __restrict__ WT,
                             int K, int N, int Npad) {
    __shared__ float tile[32][33];
    const int k0 = blockIdx.y * 32, n0 = blockIdx.x * 32;
    const int tx = threadIdx.x & 31, ty = threadIdx.x >> 5;
#pragma unroll
    for (int i = 0; i < 4; i++) {
        const int k = k0 + ty + i * 8, n = n0 + tx;
        tile[ty + i * 8][tx] = (n < N) ? W[(size_t)k * N + n] : 0.f;
    }
    __syncthreads();
    const int K2 = 3 * K;
#pragma unroll
    for (int i = 0; i < 4; i++) {
        const int n = n0 + ty + i * 8;
        const int k = k0 + tx;
        const float v = tile[tx][ty + i * 8];
        const __nv_bfloat16 hi = __float2bfloat16(v);
        const __nv_bfloat16 lo = __float2bfloat16(v - __bfloat162float(hi));
        __nv_bfloat16* row = WT + (size_t)n * K2;
        row[k] = hi; row[K + k] = lo; row[2 * K + k] = hi;
    }
}

// ---------------- fp32 SGEMM 128x128, epilogues (for up_l / fused / wo) ----------------
// epi 0: none; 1: sigmoid; (N arbitrary, guarded)
__global__ void __launch_bounds__(256) sgemm128_kernel(const float* __restrict__ A,
                                                       const float* __restrict__ W,
                                                       const float* __restrict__ bias,
                                                       float* __restrict__ Cout,
                                                       int M, int N, int K, int epi) {
    __shared__ float As[2][8][128];
    __shared__ float Bs[2][8][128];
    const int tid = threadIdx.x;
    const int tx = tid & 15, ty = tid >> 4;
    const int m0 = blockIdx.y << 7, n0 = blockIdx.x << 7;
    const int arow = tid >> 1, akq = (tid & 1) << 2;
    const int brow = tid >> 5, bcol = (tid & 31) << 2;
    const bool fullN = (n0 + 128 <= N);
    float acc[8][8] = {};
    const float* aptr = A + (size_t)(m0 + arow) * K + akq;
    {
        float4 av = *(const float4*)(aptr);
        As[0][akq + 0][arow] = av.x; As[0][akq + 1][arow] = av.y;
        As[0][akq + 2][arow] = av.z; As[0][akq + 3][arow] = av.w;
        const float* wp = W + (size_t)brow * N + n0 + bcol;
        float4 bv;
        if (fullN) bv = *(const float4*)wp;
        else {
            bv.x = (n0 + bcol + 0 < N) ? wp[0] : 0.f;
            bv.y = (n0 + bcol + 1 < N) ? wp[1] : 0.f;
            bv.z = (n0 + bcol + 2 < N) ? wp[2] : 0.f;
            bv.w = (n0 + bcol + 3 < N) ? wp[3] : 0.f;
        }
        *(float4*)&Bs[0][brow][bcol] = bv;
    }
    __syncthreads();
    int buf = 0;
    for (int k0 = 0; k0 < K; k0 += 8) {
        if (k0 + 8 < K) {
            const int nb = buf ^ 1;
            float4 av = *(const float4*)(aptr + k0 + 8);
            As[nb][akq + 0][arow] = av.x; As[nb][akq + 1][arow] = av.y;
            As[nb][akq + 2][arow] = av.z; As[nb][akq + 3][arow] = av.w;
            const float* wp = W + (size_t)(k0 + 8 + brow) * N + n0 + bcol;
            float4 bv;
            if (fullN) bv = *(const float4*)wp;
            else {
                bv.x = (n0 + bcol + 0 < N) ? wp[0] : 0.f;
                bv.y = (n0 + bcol + 1 < N) ? wp[1] : 0.f;
                bv.z = (n0 + bcol + 2 < N) ? wp[2] : 0.f;
                bv.w = (n0 + bcol + 3 < N) ? wp[3] : 0.f;
            }
            *(float4*)&Bs[nb][brow][bcol] = bv;
        }
#pragma unroll
        for (int kk = 0; kk < 8; kk++) {
            float ar[8], br[8];
            *(float4*)(ar)     = *(const float4*)&As[buf][kk][ty * 8];
            *(float4*)(ar + 4) = *(const float4*)&As[buf][kk][ty * 8 + 4];
            *(float4*)(br)     = *(const float4*)&Bs[buf][kk][tx * 8];
            *(float4*)(br + 4) = *(const float4*)&Bs[buf][kk][tx * 8 + 4];
#pragma unroll
            for (int i = 0; i < 8; i++)
#pragma unroll
                for (int j = 0; j < 8; j++) acc[i][j] = fmaf(ar[i], br[j], acc[i][j]);
        }
        __syncthreads();
        buf ^= 1;
    }
    float bj[8];
#pragma unroll
    for (int j = 0; j < 8; j++) {
        const int col = n0 + tx * 8 + j;
        bj[j] = (col < N) ? bias[col] : 0.f;
    }
#pragma unroll
    for (int i = 0; i < 8; i++) {
        const int row = m0 + ty * 8 + i;
        float* crow = Cout + (size_t)row * N;
        if (fullN) {
            float v[8];
#pragma unroll
            for (int j = 0; j < 8; j++) {
                v[j] = acc[i][j] + bj[j];
                if (epi == 1) v[j] = 1.f / (1.f + expf(-v[j]));
            }
            *(float4*)&crow[n0 + tx * 8]     = *(float4*)v;
            *(float4*)&crow[n0 + tx * 8 + 4] = *(float4*)(v + 4);
        } else {
#pragma unroll
            for (int j = 0; j < 8; j++) {
                const int col = n0 + tx * 8 + j;
                if (col < N) {
                    float v = acc[i][j] + bj[j];
                    if (epi == 1) v = 1.f / (1.f + expf(-v));
                    crow[col] = v;
                }
            }
        }
    }
}

// ---------------- HMMA GEMM bf16 split-2 (up_r / skip / down: contractive paths) ----------------
#define PADK 40

__device__ __forceinline__ uint32_t smem_u32(const void* p) {
    uint32_t a;
    asm("{ .reg .u64 t; cvta.to.shared.u64 t, %1; cvt.u32.u64 %0, t; }" : "=r"(a) : "l"(p));
    return a;
}
__device__ __forceinline__ void ldmx4(uint32_t* f, uint32_t addr) {
    asm volatile("ldmatrix.sync.aligned.m8n8.x4.shared.b16 {%0,%1,%2,%3}, [%4];"
                 : "=r"(f[0]), "=r"(f[1]), "=r"(f[2]), "=r"(f[3]) : "r"(addr));
}
__device__ __forceinline__ void mma16816(float* c, const uint32_t* a, uint32_t b0, uint32_t b1) {
    asm volatile("mma.sync.aligned.m16n8k16.row.col.f32.bf16.bf16.f32 "
                 "{%0,%1,%2,%3}, {%4,%5,%6,%7}, {%8,%9}, {%0,%1,%2,%3};"
                 : "+f"(c[0]), "+f"(c[1]), "+f"(c[2]), "+f"(c[3])
                 : "r"(a[0]), "r"(a[1]), "r"(a[2]), "r"(a[3]), "r"(b0), "r"(b1));
}

__global__ void __launch_bounds__(256, 1)
hmma_gemm_kernel(const __nv_bfloat16* __restrict__ A,
                 const __nv_bfloat16* __restrict__ BT,
                 const float* __restrict__ bias,
                 float* __restrict__ Cout,
                 int M, int N, int K2, int epi,
                 const float* __restrict__ res) {
    __shared__ __nv_bfloat16 As[2][128 * PADK];
    __shared__ __nv_bfloat16 Bs[2][128 * PADK];
    const int tid = threadIdx.x;
    const int warp = tid >> 5, lane = tid & 31;
    const int wm = (warp >> 2) * 64;
    const int wn = (warp & 3) * 32;
    const int m0 = blockIdx.y << 7, n0 = blockIdx.x << 7;

    const int r4 = tid >> 2, c4 = (tid & 3) << 3;
    float acc[16][4];
#pragma unroll
    for (int i = 0; i < 16; i++)
#pragma unroll
        for (int j = 0; j < 4; j++) acc[i][j] = 0.f;

    {
#pragma unroll
        for (int i = 0; i < 2; i++) {
            const int r = r4 + i * 64;
            *(uint4*)&As[0][r * PADK + c4] = *(const uint4*)(A + (size_t)(m0 + r) * K2 + c4);
            *(uint4*)&Bs[0][r * PADK + c4] = *(const uint4*)(BT + (size_t)(n0 + r) * K2 + c4);
        }
    }
    __syncthreads();

    const int a_row = lane & 15;
    const int a_col = (lane >> 4) << 3;
    const int b_row = (lane & 7) + ((lane & 16) >> 1);
    const int b_col = (lane & 8);

    const int S = K2 >> 5;
    for (int s = 0; s < S; s++) {
        const int cur = s & 1;
        uint4 ar[2], br[2];
        if (s + 1 < S) {
            const size_t kb = (size_t)(s + 1) << 5;
#pragma unroll
            for (int i = 0; i < 2; i++) {
                const int r = r4 + i * 64;
                ar[i] = *(const uint4*)(A + (size_t)(m0 + r) * K2 + kb + c4);
                br[i] = *(const uint4*)(BT + (size_t)(n0 + r) * K2 + kb + c4);
            }
        }
        const uint32_t a_base = smem_u32(&As[cur][0]);
        const uint32_t b_base = smem_u32(&Bs[cur][0]);
#pragma unroll
        for (int ks = 0; ks < 32; ks += 16) {
            uint32_t af[4][4], bf[2][4];
#pragma unroll
            for (int mt = 0; mt < 4; mt++)
                ldmx4(af[mt], a_base + (((wm + mt * 16 + a_row) * PADK) + ks + a_col) * 2);
#pragma unroll
            for (int np = 0; np < 2; np++)
                ldmx4(bf[np], b_base + (((wn + np * 16 + b_row) * PADK) + ks + b_col) * 2);
#pragma unroll
            for (int mt = 0; mt < 4; mt++)
#pragma unroll
                for (int nt = 0; nt < 4; nt++)
                    mma16816(acc[mt * 4 + nt], af[mt], bf[nt >> 1][(nt & 1) * 2], bf[nt >> 1][(nt & 1) * 2 + 1]);
        }
        if (s + 1 < S) {
            const int nb = cur ^ 1;
#pragma unroll
            for (int i = 0; i < 2; i++) {
                const int r = r4 + i * 64;
                *(uint4*)&As[nb][r * PADK + c4] = ar[i];
                *(uint4*)&Bs[nb][r * PADK + c4] = br[i];
            }
        }
        __syncthreads();
    }

    const int er = lane >> 2, ec = (lane & 3) << 1;
#pragma unroll
    for (int mt = 0; mt < 4; mt++) {
#pragma unroll
        for (int nt = 0; nt < 4; nt++) {
            const int col = n0 + wn + nt * 8 + ec;
            if (col >= N) continue;
            const float b0 = bias[col], b1 = bias[col + 1];
            float* a4 = acc[mt * 4 + nt];
#pragma unroll
            for (int half = 0; half < 2; half++) {
                const int row = m0 + wm + mt * 16 + er + half * 8;
                float v0 = a4[half * 2] + b0, v1 = a4[half * 2 + 1] + b1;
                if (epi == 2) {
                    const float* rr = res + (size_t)row * N + col;
                    v0 += rr[0]; v1 += rr[1];
                }
                float2 v = make_float2(v0, v1);
                *(float2*)&Cout[(size_t)row * N + col] = v;
            }
        }
    }
}

// ---------------- block reduce ----------------
__device__ __forceinline__ float block_sum_256(float v, float* red) {
    for (int o = 16; o; o >>= 1) v += __shfl_xor_sync(~0u, v, o);
    const int wid = threadIdx.x >> 5;
    if ((threadIdx.x & 31) == 0) red[wid] = v;
    __syncthreads();
    if (threadIdx.x < 32) {
        float s = (threadIdx.x < 8) ? red[threadIdx.x] : 0.f;
        for (int o = 4; o; o >>= 1) s += __shfl_xor_sync(~0u, s, o);
        if (threadIdx.x == 0) red[8] = s;
    }
    __syncthreads();
    float r = red[8];
    __syncthreads();
    return r;
}

// ---------------- LayerNorm (two-pass) ----------------
__global__ void __launch_bounds__(256) ln_kernel(const float* __restrict__ x,
                                                 const float* __restrict__ w,
                                                 const float* __restrict__ b,
                                                 float* __restrict__ y) {
    __shared__ float red[9];
    const int t = blockIdx.x;
    const float* xr = x + (size_t)t * 768;
    float v0 = xr[threadIdx.x], v1 = xr[threadIdx.x + 256], v2 = xr[threadIdx.x + 512];
    const float mean = block_sum_256(v0 + v1 + v2, red) * (1.f / 768.f);
    float d0 = v0 - mean, d1 = v1 - mean, d2 = v2 - mean;
    const float var = block_sum_256(d0 * d0 + d1 * d1 + d2 * d2, red) * (1.f / 768.f);
    const float rstd = rsqrtf(var + EPSV);
    float* yr = y + (size_t)t * 768;
    yr[threadIdx.x]       = d0 * rstd * w[threadIdx.x]       + b[threadIdx.x];
    yr[threadIdx.x + 256] = d1 * rstd * w[threadIdx.x + 256] + b[threadIdx.x + 256];
    yr[threadIdx.x + 512] = d2 * rstd * w[threadIdx.x + 512] + b[threadIdx.x + 512];
}

// ---------------- causal conv (K=4) + SiLU ----------------
__global__ void conv_silu_kernel(const float* __restrict__ xt,
                                 const float* __restrict__ cw,
                                 const float* __restrict__ cb,
                                 float* __restrict__ xc) {
    const size_t idx = (size_t)blockIdx.x * blockDim.x + threadIdx.x;
    if (idx >= (size_t)TT * UPD) return;
    const int tok = (int)(idx / UPD);
    const int t = tok % SS;
    float acc = cb[0];
    const float* base = xt + idx;
    acc += cw[3] * base[0];
    if (t >= 1) acc += cw[2] * base[-(ptrdiff_t)UPD];
    if (t >= 2) acc += cw[1] * base[-2 * (ptrdiff_t)UPD];
    if (t >= 3) acc += cw[0] * base[-3 * (ptrdiff_t)UPD];
    xc[idx] = acc / (1.f + expf(-acc));
}

// ---------------- phase A ----------------
__global__ void __launch_bounds__(256) phaseA_kernel() {
    extern __shared__ float sm[];
    float* kS = sm;
    float* vS = kS + 64 * 96;
    float* lf = vS + 64 * 96;
    float* ig = lf + 64;
    float* wC = ig + 64;
    const int tid = threadIdx.x;
    const int blk = blockIdx.x;
    const int c = blk % NCC; const int bh = blk / NCC;
    const int h = bh % NHD;  const int b = bh / NHD;
    const int tok0 = b * SS + c * CSZ;

    if (tid < 64) {
        const float* p = g_proj + (size_t)(tok0 + tid) * FUSED;
        float ip = CAPV * tanhf(p[h] / CAPV);
        float fp = CAPV * tanhf(p[NHD + h] / CAPV);
        float mx = fmaxf(ip, fp);
        ig[tid] = expf(ip - mx);
        lf[tid] = logf(expf(fp - mx) + 1e-8f);
    }
    __syncthreads();
    if (tid == 0) { float r = 0.f; for (int l = 0; l < 64; l++) { r += lf[l]; lf[l] = r; } }
    __syncthreads();
    if (tid < 64) {
        wC[tid] = expf(lf[tid] - lf[63]) * ig[tid];
        g_lf[(size_t)blk * 64 + tid] = lf[tid];
        g_ig[(size_t)blk * 64 + tid] = ig[tid];
    }
    for (int idx = tid; idx < 64 * 96; idx += 256) {
        const int l = idx / 96, e = idx - l * 96;
        const float* p = g_proj + (size_t)(tok0 + l) * FUSED + 2 * NHD + h * HD + e;
        kS[idx] = p[HID] * KSCALE;
        vS[idx] = p[2 * HID];
    }
    __syncthreads();
    for (int idx = tid; idx < 64 * 96; idx += 256) vS[idx] *= wC[idx / 96];
    __syncthreads();
    float* outC = g_C + (size_t)blk * HD * HD;
    for (int idx = tid; idx < HD * HD; idx += 256) {
        const int d = idx / HD, e = idx - d * HD;
        float s = 0.f;
#pragma unroll 8
        for (int l = 0; l < 64; l++) s += vS[l * 96 + d] * kS[l * 96 + e];
        outC[idx] = s;
    }
    if (tid < HD) {
        float s = 0.f;
#pragma unroll 8
        for (int l = 0; l < 64; l++) s += wC[l] * kS[l * 96 + tid];
        g_n[(size_t)blk * HD + tid] = s;
    }
}

// ---------------- phase B ----------------
__global__ void __launch_bounds__(256) phaseB_kernel() {
    const int bh = blockIdx.x;
    const int tid = threadIdx.x;
    float run[36];
#pragma unroll
    for (int r = 0; r < 36; r++) run[r] = 0.f;
    for (int c = 0; c < NCC; c++) {
        float* p = g_C + (size_t)(bh * NCC + c) * HD * HD;
#pragma unroll
        for (int r = 0; r < 36; r++) {
            const int idx = r * 256 + tid;
            const float t = p[idx];
            p[idx] = run[r];
            run[r] += t;
        }
    }
    if (tid < HD) {
        float rn = 0.f;
        for (int c = 0; c < NCC; c++) {
            float* p = g_n + (size_t)(bh * NCC + c) * HD;
            const float t = p[tid];
            p[tid] = rn;
            rn += t;
        }
    }
}

// ---------------- phase C ----------------
__global__ void __launch_bounds__(256) phaseC_kernel() {
    extern __shared__ float sm[];
    float* qS = sm;
    float* kS = qS + 6144;
    float* vS = kS + 6144;
    float* hS = vS + 6144;
    float* Ci = hS + 6144;
    float* sc = Ci + 9216;
    float* wS = sc + 4096;
    float* lf = wS + 4096;
    float* ig = lf + 64;
    float* nin = ig + 64;
    float* den = nin + 96;
    const int tid = threadIdx.x;
    const int blk = blockIdx.x;
    const int c = blk % NCC; const int bh = blk / NCC;
    const int h = bh % NHD;  const int b = bh / NHD;
    const int tok0 = b * SS + c * CSZ;

    for (int idx = tid; idx < 64 * 96; idx += 256) {
        const int l = idx / 96, e = idx - l * 96;
        const float* p = g_proj + (size_t)(tok0 + l) * FUSED + 2 * NHD + h * HD + e;
        qS[idx] = p[0];
        kS[idx] = p[HID] * KSCALE;
        vS[idx] = p[2 * HID];
    }
    for (int idx = tid; idx < 9216; idx += 256) Ci[idx] = g_C[(size_t)blk * 9216 + idx];
    if (tid < 96) nin[tid] = g_n[(size_t)blk * HD + tid];
    if (tid < 64) { lf[tid] = g_lf[(size_t)blk * 64 + tid]; ig[tid] = g_ig[(size_t)blk * 64 + tid]; }
    __syncthreads();

    for (int idx = tid; idx < 4096; idx += 256) {
        const int i = idx >> 6, j = idx & 63;
        const float* qi = qS + i * 96;
        const float* kj = kS + j * 96;
        float s = 0.f;
#pragma unroll 8
        for (int e = 0; e < 96; e++) s += qi[e] * kj[e];
        sc[idx] = s;
        wS[idx] = (j < i) ? ig[j] * expf(lf[i] - lf[j]) : 0.f;
    }
    __syncthreads();

    if (tid < 64) {
        const int i = tid;
        float* row = sc + i * 64;
        if (i == 0) {
            for (int j = 0; j < 64; j++) row[j] = 0.f;
        } else {
            float m = -1e30f;
            for (int j = 0; j < i; j++) m = fmaxf(m, row[j]);
            float sum = 0.f;
            for (int j = 0; j < i; j++) { float e = expf(row[j] - m); row[j] = e; sum += e; }
            const float inv = 1.f / sum;
            for (int j = 0; j < i; j++) row[j] = row[j] * inv * wS[i * 64 + j];
            for (int j = i; j < 64; j++) row[j] = 0.f;
        }
    }
    __syncthreads();

    {
        const int i = tid >> 2, dg = tid & 3;
        const float* sci = sc + i * 64;
        const float* wi  = wS + i * 64;
        const float* qi  = qS + i * 96;
        float dpart = 0.f;
#pragma unroll 4
        for (int t2 = 0; t2 < 24; t2++) {
            const int d = dg * 24 + t2;
            float hv = 0.f, nv = nin[d];
#pragma unroll 8
            for (int j = 0; j < 64; j++) {
                hv += sci[j] * vS[j * 96 + d];
                nv += wi[j]  * kS[j * 96 + d];
            }
            const float* cd = Ci + d * 96;
#pragma unroll 8
            for (int e = 0; e < 96; e++) hv += cd[e] * qi[e];
            hS[i * 96 + d] = hv;
            dpart += nv * qi[d];
        }
        den[tid] = dpart;
    }
    __syncthreads();

    for (int idx = tid; idx < 6144; idx += 256) {
        const int i = idx / 96, d = idx - i * 96;
        const float dn = fmaxf(den[i * 4] + den[i * 4 + 1] + den[i * 4 + 2] + den[i * 4 + 3], 1.f);
        g_h[(size_t)(tok0 + i) * HID + h * HD + d] = hS[idx] / dn;
    }
}

// ---------------- combine ----------------
__global__ void __launch_bounds__(256) combine_kernel(const float* __restrict__ w,
                                                      const float* __restrict__ b) {
    __shared__ float red[9];
    const int t = blockIdx.x;
    const size_t off = (size_t)t * 768 + threadIdx.x;
    float h0 = g_h[off]       * g_o[off];
    float h1 = g_h[off + 256] * g_o[off + 256];
    float h2 = g_h[off + 512] * g_o[off + 512];
    const float mean = block_sum_256(h0 + h1 + h2, red) * (1.f / 768.f);
    float d0 = h0 - mean, d1 = h1 - mean, d2 = h2 - mean;
    const float var = block_sum_256(d0 * d0 + d1 * d1 + d2 * d2, red) * (1.f / 768.f);
    const float rstd = rsqrtf(var + EPSV);
#pragma unroll
    for (int kk = 0; kk < 3; kk++) {
        const int d = threadIdx.x + kk * 256;
        const size_t o2 = (size_t)t * 768 + d;
        const float dv = (kk == 0 ? d0 : (kk == 1 ? d1 : d2));
        float g = dv * rstd * w[d] + b[d] + g_skip[o2];
        const float r = g_rt[o2];
        g *= r / (1.f + expf(-r));
        g_g[o2] = g;
    }
}

// ---------------- launch ----------------
#define GETSYMF(var, sym) float* var; { void* _p = nullptr; cudaGetSymbolAddress(&_p, sym); var = (float*)_p; }
#define GETSYMB(var, sym) __nv_bfloat16* var; { void* _p = nullptr; cudaGetSymbolAddress(&_p, sym); var = (__nv_bfloat16*)_p; }

extern "C" void kernel_launch(void* const* d_in, const int* in_sizes, int n_in,
                              void* d_out, int out_size) {
    const float* x        = (const float*)d_in[0];
    const float* ln_in_w  = (const float*)d_in[1];
    const float* ln_in_b  = (const float*)d_in[2];
    const float* ln_hid_w = (const float*)d_in[3];
    const float* ln_hid_b = (const float*)d_in[4];
    const float* up_l_w   = (const float*)d_in[5];
    const float* up_l_b   = (const float*)d_in[6];
    const float* up_r_w   = (const float*)d_in[7];
    const float* up_r_b   = (const float*)d_in[8];
    const float* down_w   = (const float*)d_in[9];
    const float* down_b   = (const float*)d_in[10];
    const float* conv_w   = (const float*)d_in[11];
    const float* conv_b   = (const float*)d_in[12];
    const float* skip_w   = (const float*)d_in[13];
    const float* skip_b   = (const float*)d_in[14];
    const float* fused_w  = (const float*)d_in[15];
    const float* fused_b  = (const float*)d_in[16];
    const float* wo_w     = (const float*)d_in[17];
    const float* wo_b     = (const float*)d_in[18];
    float* out = (float*)d_out;

    GETSYMF(p_xn, g_xn);   GETSYMF(p_xt, g_xt);   GETSYMF(p_rt, g_rt);
    GETSYMF(p_xc, g_xc);   GETSYMF(p_skip, g_skip); GETSYMF(p_proj, g_proj);
    GETSYMF(p_o, g_o);     GETSYMF(p_g, g_g);
    GETSYMB(p_Abf, g_Abf); GETSYMB(p_WT, g_WT);

    const int smemA = (2 * 64 * 96 + 3 * 64) * 4;
    const int smemC = (4 * 6144 + 9216 + 2 * 4096 + 64 + 64 + 96 + 256) * 4;
    cudaFuncSetAttribute(phaseA_kernel, cudaFuncAttributeMaxDynamicSharedMemorySize, smemA);
    cudaFuncSetAttribute(phaseC_kernel, cudaFuncAttributeMaxDynamicSharedMemorySize, smemC);

    // bf16 hmma path (only for GEMMs on contractive/post-branch paths)
    auto bgemm = [&](const float* Wf, const float* bias, float* Cp,
                     int N, int K, int epi, const float* res) {
        const int Npad = ((N + 127) / 128) * 128;
        convW_kernel<<<dim3(Npad / 32, K / 32), 256>>>(Wf, p_WT, K, N, Npad);
        hmma_gemm_kernel<<<dim3(Npad / 128, TT / 128), 256>>>(
            p_Abf, p_WT, bias, Cp, TT, N, 3 * K, epi, res);
    };

    // 1. LN
    ln_kernel<<<TT, 256>>>(x, ln_in_w, ln_in_b, p_xn);
    // 2. x_t fp32 (feeds conv -> gates/q/k/v: knife-edge-sensitive)
    sgemm128_kernel<<<dim3(UPD / 128, TT / 128), 256>>>(p_xn, up_l_w, up_l_b, p_xt, TT, UPD, D_IN, 0);
    // 3. r_t via bf16 (multiplies final output: contractive)
    convA_kernel<<<dim3(D_IN / 256, TT), 256>>>(p_xn, p_Abf, D_IN);
    bgemm(up_r_w, up_r_b, p_rt, HID, D_IN, 0, nullptr);
    // 4. conv
    conv_silu_kernel<<<(int)(((size_t)TT * UPD + 255) / 256), 256>>>(p_xt, conv_w, conv_b, p_xc);
    // 5. o fp32 (multiplies h before the saturating LN: knife-edge-sensitive)
    sgemm128_kernel<<<dim3(HID / 128, TT / 128), 256>>>(p_xt, wo_w, wo_b, p_o, TT, HID, UPD, 1);
    // 6. proj fp32 (q/k/v/gates: knife-edge-sensitive)
    sgemm128_kernel<<<dim3((FUSED + 127) / 128, TT / 128), 256>>>(p_xc, fused_w, fused_b, p_proj, TT, FUSED, UPD, 0);
    // 7. skip via bf16 (additive after saturation branch)
    convA_kernel<<<dim3(UPD / 256, TT), 256>>>(p_xc, p_Abf, UPD);
    bgemm(skip_w, skip_b, p_skip, HID, UPD, 0, nullptr);
    // 8. attention
    phaseA_kernel<<<NBLK, 256, smemA>>>();
    phaseB_kernel<<<NBH, 256>>>();
    phaseC_kernel<<<NBLK, 256, smemC>>>();
    // 9. combine
    combine_kernel<<<TT, 256>>>(ln_hid_w, ln_hid_b);
    // 10. down via bf16 + residual
    convA_kernel<<<dim3(HID / 256, TT), 256>>>(p_g, p_Abf, HID);
    bgemm(down_w, down_b, out, D_IN, HID, 2, x);
}